// round 10
// baseline (speedup 1.0000x reference)
#include <cuda_runtime.h>
#include <cuda_fp16.h>
#include <cstdint>

// ---------------- problem constants ----------------
#define CIN     2112
#define COUT    192
#define HW      49
#define M_TOTAL 12544          // 256*49
#define BM      64
#define BN      96
#define BK      64
#define CHUNKS  33             // 2112/64
#define NTH     256
#define EPS_BN  1e-5f

// smem: row stride 144B (64 halfs + 16B pad; 16B-aligned for ldmatrix)
#define RSTB    144
#define A_STAGE (BM * RSTB)            // 9216 B
#define B_STAGE (BN * RSTB)            // 13824 B
#define SM_A    0                      // 2 stages: 18432 B
#define SM_B    (2 * A_STAGE)          // 3 stages: 41472 B
#define SMEM_TOTAL (SM_B + 3 * B_STAGE)  // 59904 B -> 3 CTAs/SM
// epilogue C staging reuses smem from 0: 96 x 66 floats = 25344 B
#define CST     66

// ---------------- persistent scratch ----------------
__device__ __half g_wh[COUT * CIN];    // W fp16, k-major
__device__ float2 g_bn[CIN];           // {scale, shift}

__global__ void prep_k(const float* __restrict__ W,
                       const float* __restrict__ gamma, const float* __restrict__ beta,
                       const float* __restrict__ mean,  const float* __restrict__ var) {
    int i = blockIdx.x * blockDim.x + threadIdx.x;
    if (i < COUT * CIN) g_wh[i] = __float2half_rn(W[i]);
    if (i < CIN) {
        float inv = rsqrtf(var[i] + EPS_BN);
        float s = gamma[i] * inv;
        g_bn[i] = make_float2(s, fmaf(-mean[i], s, beta[i]));
    }
}

// ---------------- helpers ----------------
__device__ __forceinline__ uint32_t smem_u32(const void* p) {
    uint32_t a;
    asm("{ .reg .u64 t; cvta.to.shared.u64 t, %1; cvt.u32.u64 %0, t; }" : "=r"(a) : "l"(p));
    return a;
}
__device__ __forceinline__ void cp16(uint32_t dst, const void* src) {
    asm volatile("cp.async.cg.shared.global [%0], [%1], 16;" :: "r"(dst), "l"(src));
}
__device__ __forceinline__ void ldm_x4(uint32_t* r, uint32_t addr) {
    asm volatile("ldmatrix.sync.aligned.m8n8.x4.shared.b16 {%0,%1,%2,%3}, [%4];"
                 : "=r"(r[0]), "=r"(r[1]), "=r"(r[2]), "=r"(r[3]) : "r"(addr));
}
__device__ __forceinline__ void ldm_x2(uint32_t* r, uint32_t addr) {
    asm volatile("ldmatrix.sync.aligned.m8n8.x2.shared.b16 {%0,%1}, [%2];"
                 : "=r"(r[0]), "=r"(r[1]) : "r"(addr));
}

// ---------------- fused BN+ReLU + fp16 GEMM ----------------
// C[M=12544, N=192] = relu(x*s+t)[M, K] * W[N, K]^T ; grid 392 = 196 m x 2 n
__global__ __launch_bounds__(NTH, 3)
void gemm_k(const float* __restrict__ x, float* __restrict__ out) {
    extern __shared__ char smem[];
    const uint32_t sA = smem_u32(smem) + SM_A;
    const uint32_t sB = smem_u32(smem) + SM_B;

    const int tid  = threadIdx.x;
    const int lane = tid & 31, warp = tid >> 5;
    const int wm = warp & 1, wn = warp >> 1;        // 2 x 4 warp grid
    const int g  = lane >> 2, tq = lane & 3;

    const int m0 = (blockIdx.x >> 1) * BM;
    const int n0 = (blockIdx.x & 1) * BN;

    // A loader: thread -> (m = tid&63, 16 k at kq*16)
    const int am = tid & 63, kq = tid >> 6;
    const int mg = m0 + am;
    const float* xp = x + (size_t)(mg / HW) * ((size_t)CIN * HW) + (mg % HW)
                        + (size_t)(kq * 16) * HW;

    const __half* bsrc = g_wh + (size_t)n0 * CIN;

    // ldmatrix per-thread offsets within a stage
    const uint32_t offA = (uint32_t)(wm * 32 + (lane & 15)) * RSTB + (uint32_t)(lane >> 4) * 16u;
    const uint32_t offB01 = (uint32_t)(wn * 24 + ((lane >> 4) << 3) + (lane & 7)) * RSTB
                          + (uint32_t)((lane >> 3) & 1) * 16u;
    const int l15 = lane & 15;
    const uint32_t offB2 = (uint32_t)(wn * 24 + 16 + (l15 & 7)) * RSTB
                         + (uint32_t)(l15 >> 3) * 16u;

    float acc[2][3][4] = {};
    float ar[16];

    // B cp.async for one chunk: 96 rows x 8 packets = 768 = 3 x 256
    auto issueB = [&](int c) {
        const uint32_t bb = sB + (c % 3) * B_STAGE;
        const __half* bw = bsrc + (size_t)c * BK;
        #pragma unroll
        for (int i = 0; i < 3; i++) {
            const int q = tid + i * NTH, r = q >> 3, p = q & 7;
            cp16(bb + r * RSTB + p * 16, bw + (size_t)r * CIN + p * 8);
        }
    };
    // A: BN+ReLU+cvt+STS for chunk c from regs
    auto stsA = [&](int c) {
        const int k0 = c * BK + kq * 16;
        __half h[16];
        #pragma unroll
        for (int j = 0; j < 16; j++) {
            const float2 s = __ldg(&g_bn[k0 + j]);
            h[j] = __float2half_rn(fmaxf(fmaf(ar[j], s.x, s.y), 0.f));
        }
        char* ab = smem + SM_A + (c & 1) * A_STAGE + am * RSTB + kq * 32;
        *(uint4*)(ab)      = *(uint4*)&h[0];
        *(uint4*)(ab + 16) = *(uint4*)&h[8];
    };

    // ---- prologue: B(0), B(1) in flight; A(0) staged ----
    issueB(0);
    asm volatile("cp.async.commit_group;");
    issueB(1);
    asm volatile("cp.async.commit_group;");
    #pragma unroll
    for (int j = 0; j < 16; j++) ar[j] = __ldg(xp + (size_t)j * HW);
    stsA(0);

    // ---- main loop ----
    // iter t: wait(B t); sync; LDG A(t+1); issue B(t+2); compute(t); STS A(t+1)
    #pragma unroll 1
    for (int t = 0; t < CHUNKS; t++) {
        asm volatile("cp.async.wait_group 1;");   // B(t) resident (issued at t-2)
        __syncthreads();                          // A(t) STS + B(t) visible; WAR fences

        const bool more = (t + 1 < CHUNKS);
        if (more) {
            const float* xp2 = xp + (size_t)(t + 1) * BK * HW;
            #pragma unroll
            for (int j = 0; j < 16; j++) ar[j] = __ldg(xp2 + (size_t)j * HW);
        }
        if (t + 2 < CHUNKS) issueB(t + 2);
        asm volatile("cp.async.commit_group;");   // possibly empty: uniform accounting

        // compute chunk t: 4 k16 steps
        const uint32_t aBase = sA + (t & 1) * A_STAGE;
        const uint32_t bBase = sB + (t % 3) * B_STAGE;
        #pragma unroll
        for (int s = 0; s < 4; s++) {
            uint32_t a[2][4], b01[4], b2[2];
            ldm_x4(a[0], aBase + offA + s * 32);
            ldm_x4(a[1], aBase + offA + 16 * RSTB + s * 32);
            ldm_x4(b01, bBase + offB01 + s * 32);
            ldm_x2(b2,  bBase + offB2  + s * 32);
            const uint32_t* bf[3] = { &b01[0], &b01[2], &b2[0] };
            #pragma unroll
            for (int mi = 0; mi < 2; mi++)
                #pragma unroll
                for (int ni = 0; ni < 3; ni++) {
                    asm volatile(
                        "mma.sync.aligned.m16n8k16.row.col.f32.f16.f16.f32 "
                        "{%0,%1,%2,%3},{%4,%5,%6,%7},{%8,%9},{%0,%1,%2,%3};"
                        : "+f"(acc[mi][ni][0]), "+f"(acc[mi][ni][1]),
                          "+f"(acc[mi][ni][2]), "+f"(acc[mi][ni][3])
                        : "r"(a[mi][0]), "r"(a[mi][1]), "r"(a[mi][2]), "r"(a[mi][3]),
                          "r"(bf[ni][0]), "r"(bf[ni][1]));
                }
        }

        if (more) stsA(t + 1);
    }

    // ---- epilogue: acc -> Cs[n][m] in smem -> coalesced STG ----
    __syncthreads();                               // all compute done before smem reuse
    float* Cs = (float*)smem;                      // 96 x 66 floats
    #pragma unroll
    for (int mi = 0; mi < 2; mi++)
        #pragma unroll
        for (int hh = 0; hh < 2; hh++) {
            const int mloc = wm * 32 + mi * 16 + g + hh * 8;
            #pragma unroll
            for (int ni = 0; ni < 3; ni++) {
                const int nloc = wn * 24 + ni * 8 + tq * 2;
                Cs[nloc * CST + mloc]       = acc[mi][ni][hh * 2 + 0];
                Cs[(nloc + 1) * CST + mloc] = acc[mi][ni][hh * 2 + 1];
            }
        }
    __syncthreads();

    // each warp writes 12 n-rows; lane covers m = 2*lane, 2*lane+1 (hw-contiguous)
    {
        const int mg0 = m0 + lane * 2;
        const int b0_ = mg0 / HW,        hw0 = mg0 - b0_ * HW;
        const int b1_ = (mg0 + 1) / HW,  hw1 = (mg0 + 1) - b1_ * HW;
        #pragma unroll
        for (int r = 0; r < 12; r++) {
            const int nn = n0 + warp * 12 + r;
            const float2 v = *(const float2*)&Cs[(warp * 12 + r) * CST + lane * 2];
            out[((size_t)b0_ * COUT + nn) * HW + hw0] = v.x;
            out[((size_t)b1_ * COUT + nn) * HW + hw1] = v.y;
        }
    }
}

extern "C" void kernel_launch(void* const* d_in, const int* in_sizes, int n_in,
                              void* d_out, int out_size) {
    const float* x     = (const float*)d_in[0];
    const float* gamma = (const float*)d_in[1];
    const float* beta  = (const float*)d_in[2];
    const float* mean  = (const float*)d_in[3];
    const float* var   = (const float*)d_in[4];
    const float* W     = (const float*)d_in[5];
    float* out = (float*)d_out;

    prep_k<<<(COUT * CIN + 255) / 256, 256>>>(W, gamma, beta, mean, var);
    cudaFuncSetAttribute(gemm_k, cudaFuncAttributeMaxDynamicSharedMemorySize, SMEM_TOTAL);
    gemm_k<<<(M_TOTAL / BM) * 2, NTH, SMEM_TOTAL>>>(x, out);
}

// round 11
// speedup vs baseline: 1.1738x; 1.1738x over previous
#include <cuda_runtime.h>
#include <cuda_fp16.h>
#include <cstdint>

// ---------------- problem constants ----------------
#define CIN     2112
#define COUT    192
#define HW      49
#define M_TOTAL 12544          // 256*49
#define BM      64
#define BN      96
#define BK      64
#define CHUNKS  33             // 2112/64
#define NTH     128            // 4 warps, warp tile 32x48
#define EPS_BN  1e-5f

// smem: row stride 144B (64 halfs + 16B pad; 16B-aligned, conflict-free)
#define RSTB    144
#define A_STAGE (BM * RSTB)            // 9216 B
#define B_STAGE (BN * RSTB)            // 13824 B
#define SM_BNS  0                      // float2[2112] = 16896 B
#define SM_A    16896                  // 2 stages
#define SM_B    (SM_A + 2 * A_STAGE)   // 2 stages
#define SMEM_TOTAL (SM_B + 2 * B_STAGE)  // 62976 B -> 3 CTAs/SM
#define CST     66                     // epilogue Cs row stride (floats)

// ---------------- persistent scratch ----------------
__device__ __half g_wh[COUT * CIN];    // W fp16, k-major

__global__ void prep_w_k(const float* __restrict__ W) {
    int i = blockIdx.x * blockDim.x + threadIdx.x;
    if (i < COUT * CIN) g_wh[i] = __float2half_rn(W[i]);
}

// ---------------- helpers ----------------
__device__ __forceinline__ uint32_t smem_u32(const void* p) {
    uint32_t a;
    asm("{ .reg .u64 t; cvta.to.shared.u64 t, %1; cvt.u32.u64 %0, t; }" : "=r"(a) : "l"(p));
    return a;
}
__device__ __forceinline__ void cp16(uint32_t dst, const void* src) {
    asm volatile("cp.async.cg.shared.global [%0], [%1], 16;" :: "r"(dst), "l"(src));
}
__device__ __forceinline__ void ldm_x4(uint32_t* r, uint32_t addr) {
    asm volatile("ldmatrix.sync.aligned.m8n8.x4.shared.b16 {%0,%1,%2,%3}, [%4];"
                 : "=r"(r[0]), "=r"(r[1]), "=r"(r[2]), "=r"(r[3]) : "r"(addr));
}

// ---------------- fused BN+ReLU + fp16 GEMM ----------------
// C[M=12544, N=192] = relu(x*s+t)[M, K] * W[N, K]^T ; grid 392 = 196 m x 2 n
__global__ __launch_bounds__(NTH, 3)
void gemm_k(const float* __restrict__ x,
            const float* __restrict__ gamma, const float* __restrict__ beta,
            const float* __restrict__ mean,  const float* __restrict__ var,
            float* __restrict__ out) {
    extern __shared__ char smem[];
    float2* bns = (float2*)(smem + SM_BNS);
    const uint32_t sA = smem_u32(smem) + SM_A;
    const uint32_t sB = smem_u32(smem) + SM_B;

    const int tid  = threadIdx.x;
    const int lane = tid & 31, warp = tid >> 5;     // 4 warps
    const int wm = warp & 1, wn = warp >> 1;        // 2 x 2 warp grid, tile 32x48
    const int g  = lane >> 2, tq = lane & 3;

    const int m0 = (blockIdx.x >> 1) * BM;
    const int n0 = (blockIdx.x & 1) * BN;

    // A loader: thread -> (m = tid&63, 32 k at kh*32); warps 0,1: kh=0; 2,3: kh=1
    const int am = tid & 63, kh = tid >> 6;
    const int mg = m0 + am;
    const float* xp = x + (size_t)(mg / HW) * ((size_t)CIN * HW) + (mg % HW)
                        + (size_t)(kh * 32) * HW;

    const __half* bsrc = g_wh + (size_t)n0 * CIN;

    // ldmatrix per-thread offsets within a stage
    const uint32_t offA = (uint32_t)(wm * 32 + (lane & 15)) * RSTB + (uint32_t)(lane >> 4) * 16u;
    uint32_t offB[3];
    #pragma unroll
    for (int j = 0; j < 3; j++)
        offB[j] = (uint32_t)(wn * 48 + j * 16 + ((lane >> 4) << 3) + (lane & 7)) * RSTB
                + (uint32_t)((lane >> 3) & 1) * 16u;

    float acc[2][6][4] = {};
    float ar[32];

    // B cp.async for one chunk: 96 rows x 8 packets = 768 = 6 x 128
    auto issueB = [&](int c, uint32_t bb) {
        const __half* bw = bsrc + (size_t)c * BK;
        #pragma unroll
        for (int i = 0; i < 6; i++) {
            const int q = tid + i * NTH, r = q >> 3, p = q & 7;
            cp16(bb + r * RSTB + p * 16, bw + (size_t)r * CIN + p * 8);
        }
    };
    // A: BN+ReLU+cvt+STS for chunk c from regs (32 halfs = 4 x uint4)
    auto stsA = [&](int c) {
        const int k0 = c * BK + kh * 32;
        __half h[32];
        #pragma unroll
        for (int j = 0; j < 32; j++) {
            const float2 s = bns[k0 + j];
            h[j] = __float2half_rn(fmaxf(fmaf(ar[j], s.x, s.y), 0.f));
        }
        char* ab = smem + SM_A + (c & 1) * A_STAGE + am * RSTB + kh * 64;
        #pragma unroll
        for (int i = 0; i < 4; i++)
            *(uint4*)(ab + i * 16) = *(uint4*)&h[i * 8];
    };

    // ---- prologue ----
    issueB(0, sB);
    asm volatile("cp.async.commit_group;");
    #pragma unroll
    for (int j = 0; j < 32; j++) ar[j] = __ldg(xp + (size_t)j * HW);
    for (int c = tid; c < CIN; c += NTH) {
        float inv = rsqrtf(var[c] + EPS_BN);
        float s = gamma[c] * inv;
        bns[c] = make_float2(s, fmaf(-mean[c], s, beta[c]));
    }
    __syncthreads();                                 // bns ready
    stsA(0);
    asm volatile("cp.async.wait_group 0;");
    __syncthreads();

    // ---- main loop (R9 structure): LDG A(t+1); cp B(t+1); compute(t); STS A(t+1); wait; sync
    #pragma unroll 1
    for (int t = 0; t < CHUNKS; t++) {
        const int cur = t & 1, nxt = cur ^ 1;
        const bool more = (t + 1 < CHUNKS);

        if (more) {
            const float* xp2 = xp + (size_t)(t + 1) * BK * HW;
            #pragma unroll
            for (int j = 0; j < 32; j++) ar[j] = __ldg(xp2 + (size_t)j * HW);
            issueB(t + 1, sB + nxt * B_STAGE);
        }
        asm volatile("cp.async.commit_group;");

        // compute chunk t: 4 k16 steps, warp tile 32x48
        const uint32_t aBase = sA + cur * A_STAGE;
        const uint32_t bBase = sB + cur * B_STAGE;
        #pragma unroll
        for (int s = 0; s < 4; s++) {
            uint32_t a[2][4], b[3][4];
            ldm_x4(a[0], aBase + offA + s * 32);
            ldm_x4(a[1], aBase + offA + 16 * RSTB + s * 32);
            #pragma unroll
            for (int j = 0; j < 3; j++) ldm_x4(b[j], bBase + offB[j] + s * 32);
            #pragma unroll
            for (int mi = 0; mi < 2; mi++)
                #pragma unroll
                for (int ni = 0; ni < 6; ni++) {
                    const uint32_t* bf = &b[ni >> 1][(ni & 1) * 2];
                    asm volatile(
                        "mma.sync.aligned.m16n8k16.row.col.f32.f16.f16.f32 "
                        "{%0,%1,%2,%3},{%4,%5,%6,%7},{%8,%9},{%0,%1,%2,%3};"
                        : "+f"(acc[mi][ni][0]), "+f"(acc[mi][ni][1]),
                          "+f"(acc[mi][ni][2]), "+f"(acc[mi][ni][3])
                        : "r"(a[mi][0]), "r"(a[mi][1]), "r"(a[mi][2]), "r"(a[mi][3]),
                          "r"(bf[0]), "r"(bf[1]));
                }
        }

        if (more) stsA(t + 1);
        asm volatile("cp.async.wait_group 0;");
        __syncthreads();
    }

    // ---- epilogue: acc -> Cs[n][m] in smem -> coalesced STG ----
    float* Cs = (float*)smem;                        // 96 x 66 floats (reuses smem)
    #pragma unroll
    for (int mi = 0; mi < 2; mi++)
        #pragma unroll
        for (int hh = 0; hh < 2; hh++) {
            const int mloc = wm * 32 + mi * 16 + g + hh * 8;
            #pragma unroll
            for (int ni = 0; ni < 6; ni++) {
                const int nloc = wn * 48 + ni * 8 + tq * 2;
                Cs[nloc * CST + mloc]       = acc[mi][ni][hh * 2 + 0];
                Cs[(nloc + 1) * CST + mloc] = acc[mi][ni][hh * 2 + 1];
            }
        }
    __syncthreads();

    // each warp writes 24 n-rows; lane covers m = 2*lane, 2*lane+1 (hw-contiguous)
    {
        const int mg0 = m0 + lane * 2;
        const int b0_ = mg0 / HW,        hw0 = mg0 - b0_ * HW;
        const int b1_ = (mg0 + 1) / HW,  hw1 = (mg0 + 1) - b1_ * HW;
        #pragma unroll
        for (int r = 0; r < 24; r++) {
            const int nn = n0 + warp * 24 + r;
            const float2 v = *(const float2*)&Cs[(warp * 24 + r) * CST + lane * 2];
            out[((size_t)b0_ * COUT + nn) * HW + hw0] = v.x;
            out[((size_t)b1_ * COUT + nn) * HW + hw1] = v.y;
        }
    }
}

extern "C" void kernel_launch(void* const* d_in, const int* in_sizes, int n_in,
                              void* d_out, int out_size) {
    const float* x     = (const float*)d_in[0];
    const float* gamma = (const float*)d_in[1];
    const float* beta  = (const float*)d_in[2];
    const float* mean  = (const float*)d_in[3];
    const float* var   = (const float*)d_in[4];
    const float* W     = (const float*)d_in[5];
    float* out = (float*)d_out;

    prep_w_k<<<(COUT * CIN + 255) / 256, 256>>>(W);
    cudaFuncSetAttribute(gemm_k, cudaFuncAttributeMaxDynamicSharedMemorySize, SMEM_TOTAL);
    gemm_k<<<(M_TOTAL / BM) * 2, NTH, SMEM_TOTAL>>>(x, gamma, beta, mean, var, out);
}